// round 1
// baseline (speedup 1.0000x reference)
#include <cuda_runtime.h>
#include <math.h>

#define Bb 4
#define Ss 2048
#define Ee 1024
#define Hh 16
#define Dd 64
#define FFf 4096
#define NT (Bb*Ss)          // 8192 tokens
#define HALF_WIN 128

// ------------------------- scratch (device globals; no allocations) -------------------------
__device__ float g_h   [NT * Ee];        // LN output (h1, then reused for h2)
__device__ float g_qkv [NT * 3 * Ee];    // QKV projection
__device__ float g_q   [Bb * Hh * Ss * Dd];
__device__ float g_k   [Bb * Hh * Ss * Dd];
__device__ float g_v   [Bb * Hh * Ss * Dd];
__device__ float g_attn[NT * Ee];        // attention output, [B,S,H,D] flattened
__device__ float g_x1  [NT * Ee];        // residual 1
__device__ float g_gate[NT * FFf];       // gelu(gate), then gate*val in-place

// ------------------------- block reduce helper -------------------------
__device__ __forceinline__ float blockReduceSum(float v, float* red) {
    #pragma unroll
    for (int o = 16; o > 0; o >>= 1) v += __shfl_xor_sync(0xffffffffu, v, o);
    if ((threadIdx.x & 31) == 0) red[threadIdx.x >> 5] = v;
    __syncthreads();
    float t = 0.f;
    #pragma unroll
    for (int i = 0; i < 8; i++) t += red[i];
    __syncthreads();
    return t;
}

// ------------------------- LayerNorm: one block per token -------------------------
__global__ __launch_bounds__(256) void ln_kernel(
    const float* __restrict__ x, const float* __restrict__ gamma,
    const float* __restrict__ beta, float* __restrict__ out)
{
    __shared__ float red[8];
    const int t = blockIdx.x;
    const int tid = threadIdx.x;
    const float4 v = ((const float4*)(x + (size_t)t * Ee))[tid];

    float s = v.x + v.y + v.z + v.w;
    s = blockReduceSum(s, red);
    const float mu = s * (1.0f / Ee);

    float dx = (v.x-mu)*(v.x-mu) + (v.y-mu)*(v.y-mu) + (v.z-mu)*(v.z-mu) + (v.w-mu)*(v.w-mu);
    dx = blockReduceSum(dx, red);
    const float inv = rsqrtf(dx * (1.0f / Ee) + 1e-5f);

    const float4 g4 = ((const float4*)gamma)[tid];
    const float4 b4 = ((const float4*)beta)[tid];
    float4 r;
    r.x = (v.x - mu) * inv * g4.x + b4.x;
    r.y = (v.y - mu) * inv * g4.y + b4.y;
    r.z = (v.z - mu) * inv * g4.z + b4.z;
    r.w = (v.w - mu) * inv * g4.w + b4.w;
    ((float4*)(out + (size_t)t * Ee))[tid] = r;
}

// ------------------------- SGEMM 128x128x8, 256 threads, 8x8 micro -------------------------
// MODE 0: C = A*W + bias
// MODE 1: C = extra + A*W + bias           (residual)
// MODE 2: C = gelu(A*W + bias)             (exact gelu, x*Phi(x))
// MODE 3: C = (A*W + bias) * extra         (gate multiply; extra may alias C)
template<int MODE>
__global__ __launch_bounds__(256) void sgemm128(
    const float* __restrict__ A, const float* __restrict__ W,
    const float* __restrict__ bias, const float* __restrict__ extra,
    float* __restrict__ C, int M, int N, int K)
{
    __shared__ float As[8][132];
    __shared__ float Bs[8][132];
    const int tid = threadIdx.x;
    const int bx = blockIdx.x, by = blockIdx.y;
    const int tx = tid & 15, ty = tid >> 4;

    float acc[8][8];
    #pragma unroll
    for (int i = 0; i < 8; i++)
        #pragma unroll
        for (int j = 0; j < 8; j++) acc[i][j] = 0.f;

    const int arow = tid >> 1;
    const int acol = (tid & 1) << 2;
    const int brow = tid >> 5;
    const int bcol = (tid & 31) << 2;

    const float* Ap = A + (size_t)(by * 128 + arow) * K + acol;
    const float* Bp = W + (size_t)brow * N + bx * 128 + bcol;

    for (int k0 = 0; k0 < K; k0 += 8) {
        const float4 a4 = *(const float4*)Ap;
        const float4 b4 = *(const float4*)Bp;
        As[acol+0][arow] = a4.x;
        As[acol+1][arow] = a4.y;
        As[acol+2][arow] = a4.z;
        As[acol+3][arow] = a4.w;
        *(float4*)&Bs[brow][bcol] = b4;
        __syncthreads();
        #pragma unroll
        for (int kk = 0; kk < 8; kk++) {
            float ar[8], br[8];
            *(float4*)&ar[0] = *(const float4*)&As[kk][ty * 8];
            *(float4*)&ar[4] = *(const float4*)&As[kk][ty * 8 + 4];
            *(float4*)&br[0] = *(const float4*)&Bs[kk][tx * 8];
            *(float4*)&br[4] = *(const float4*)&Bs[kk][tx * 8 + 4];
            #pragma unroll
            for (int i = 0; i < 8; i++)
                #pragma unroll
                for (int j = 0; j < 8; j++)
                    acc[i][j] += ar[i] * br[j];
        }
        __syncthreads();
        Ap += 8;
        Bp += (size_t)8 * N;
    }

    #pragma unroll
    for (int i = 0; i < 8; i++) {
        const int row = by * 128 + ty * 8 + i;
        const size_t base = (size_t)row * N + bx * 128 + tx * 8;
        #pragma unroll
        for (int j0 = 0; j0 < 8; j0 += 4) {
            const size_t off = base + j0;
            const int col = bx * 128 + tx * 8 + j0;
            const float4 bi = *(const float4*)(bias + col);
            float4 r;
            r.x = acc[i][j0+0] + bi.x;
            r.y = acc[i][j0+1] + bi.y;
            r.z = acc[i][j0+2] + bi.z;
            r.w = acc[i][j0+3] + bi.w;
            if (MODE == 1) {
                const float4 e = *(const float4*)(extra + off);
                r.x += e.x; r.y += e.y; r.z += e.z; r.w += e.w;
            }
            if (MODE == 2) {
                r.x = r.x * normcdff(r.x);
                r.y = r.y * normcdff(r.y);
                r.z = r.z * normcdff(r.z);
                r.w = r.w * normcdff(r.w);
            }
            if (MODE == 3) {
                const float4 e = *(const float4*)(extra + off);
                r.x *= e.x; r.y *= e.y; r.z *= e.z; r.w *= e.w;
            }
            *(float4*)(C + off) = r;
        }
    }
}

// ------------------------- RoPE + split QKV -> [B,H,S,D] -------------------------
__global__ void rope_split_kernel(
    const float* __restrict__ qkv,
    float* __restrict__ Q, float* __restrict__ K, float* __restrict__ V)
{
    const int idx = blockIdx.x * blockDim.x + threadIdx.x;
    const int total = Bb * Hh * Ss * 32;
    if (idx >= total) return;
    const int dp = idx & 31;
    const int t  = idx >> 5;
    const int s  = t & (Ss - 1);
    const int bh = t >> 11;                 // t / S
    const int h  = bh & (Hh - 1);
    const int b  = bh >> 4;                 // bh / H

    const float* base = qkv + (size_t)(b * Ss + s) * (3 * Ee) + h * Dd;
    const float q1 = base[dp],          q2 = base[dp + 32];
    const float k1 = base[Ee + dp],     k2 = base[Ee + dp + 32];
    const float v1 = base[2*Ee + dp],   v2 = base[2*Ee + dp + 32];

    const float inv = (float)exp(-(double)(2 * dp) / 64.0 * log(10000.0));
    const float ang = (float)s * inv;
    float sn, cs;
    sincosf(ang, &sn, &cs);

    const size_t o = ((size_t)bh * Ss + s) * Dd + dp;
    Q[o]      = q1 * cs - q2 * sn;
    Q[o + 32] = q2 * cs + q1 * sn;
    K[o]      = k1 * cs - k2 * sn;
    K[o + 32] = k2 * cs + k1 * sn;
    V[o]      = v1;
    V[o + 32] = v2;
}

// ------------------------- windowed flash attention -------------------------
// grid: (S/64, B*H). 256 threads. 64-query tile, 5 key chunks of 64.
// dyn smem: QsT[64][68] + Ks[64][68] + Vs[64][68] + SsT[64][68] = 69632 B
__global__ __launch_bounds__(256) void attn_kernel(
    const float* __restrict__ Qg, const float* __restrict__ Kg,
    const float* __restrict__ Vg, float* __restrict__ AO)
{
    extern __shared__ float sm[];
    float* QsT = sm;                 // [d][q]   (transposed)
    float* Ks  = sm + 64 * 68;       // [key][d]
    float* Vs  = Ks + 64 * 68;       // [key][d]
    float* SsT = Vs + 64 * 68;       // [key][q] (transposed scores)

    const int tid = threadIdx.x;
    const int q0  = blockIdx.x * 64;
    const int bh  = blockIdx.y;
    const int b   = bh >> 4;
    const int h   = bh & (Hh - 1);
    const float* Qb = Qg + (size_t)bh * Ss * Dd;
    const float* Kb = Kg + (size_t)bh * Ss * Dd;
    const float* Vb = Vg + (size_t)bh * Ss * Dd;

    // stage Q transposed
    for (int p = tid; p < 1024; p += 256) {
        const int qr = p >> 4, d4 = (p & 15) << 2;
        const float4 v = *(const float4*)(Qb + (size_t)(q0 + qr) * Dd + d4);
        QsT[(d4+0)*68 + qr] = v.x;
        QsT[(d4+1)*68 + qr] = v.y;
        QsT[(d4+2)*68 + qr] = v.z;
        QsT[(d4+3)*68 + qr] = v.w;
    }

    const int ckey = tid >> 2;            // phase-A: key handled by this thread
    const int crg  = (tid & 3) << 4;      // phase-A: 16-query group
    const int srow = tid >> 2;            // phase-B: query row
    const int sd0  = (tid & 3) << 4;      // phase-B: 16-dim group

    float m = -1e30f, l = 0.f;
    float oacc[16];
    #pragma unroll
    for (int i = 0; i < 16; i++) oacc[i] = 0.f;

    __syncthreads();

    for (int c = 0; c < 5; c++) {
        const int kc0 = q0 - HALF_WIN + c * 64;
        // stage K/V chunk (guarded)
        for (int p = tid; p < 1024; p += 256) {
            const int kr = p >> 4, d4 = (p & 15) << 2;
            const int kg = kc0 + kr;
            float4 kv = make_float4(0.f, 0.f, 0.f, 0.f), vv = kv;
            if (kg >= 0 && kg < Ss) {
                kv = *(const float4*)(Kb + (size_t)kg * Dd + d4);
                vv = *(const float4*)(Vb + (size_t)kg * Dd + d4);
            }
            *(float4*)&Ks[kr * 68 + d4] = kv;
            *(float4*)&Vs[kr * 68 + d4] = vv;
        }
        __syncthreads();

        // scores: thread = (1 key) x (16 queries)
        float sc[16];
        #pragma unroll
        for (int i = 0; i < 16; i++) sc[i] = 0.f;
        #pragma unroll 8
        for (int d = 0; d < 64; d++) {
            const float kval = Ks[ckey * 68 + d];
            const float4 qa = *(const float4*)&QsT[d * 68 + crg];
            const float4 qb2 = *(const float4*)&QsT[d * 68 + crg + 4];
            const float4 qc = *(const float4*)&QsT[d * 68 + crg + 8];
            const float4 qd = *(const float4*)&QsT[d * 68 + crg + 12];
            sc[0]  += kval * qa.x;  sc[1]  += kval * qa.y;
            sc[2]  += kval * qa.z;  sc[3]  += kval * qa.w;
            sc[4]  += kval * qb2.x; sc[5]  += kval * qb2.y;
            sc[6]  += kval * qb2.z; sc[7]  += kval * qb2.w;
            sc[8]  += kval * qc.x;  sc[9]  += kval * qc.y;
            sc[10] += kval * qc.z;  sc[11] += kval * qc.w;
            sc[12] += kval * qd.x;  sc[13] += kval * qd.y;
            sc[14] += kval * qd.z;  sc[15] += kval * qd.w;
        }
        const int kg = kc0 + ckey;
        const bool kvalid = (kg >= 0 && kg < Ss);
        #pragma unroll
        for (int i = 0; i < 16; i++) {
            const int qg = q0 + crg + i;
            const bool ok = kvalid && (abs(qg - kg) <= HALF_WIN);
            SsT[ckey * 68 + crg + i] = ok ? sc[i] * 0.125f : -1e9f;
        }
        __syncthreads();

        // online softmax + P*V: thread = (1 query) x (16 dims)
        float cmax = -1e30f;
        #pragma unroll 8
        for (int j = 0; j < 64; j++) cmax = fmaxf(cmax, SsT[j * 68 + srow]);
        if (cmax > -1e8f) {
            const float mnew = fmaxf(m, cmax);
            const float corr = __expf(m - mnew);
            m = mnew;
            l *= corr;
            #pragma unroll
            for (int i = 0; i < 16; i++) oacc[i] *= corr;
            #pragma unroll 4
            for (int j = 0; j < 64; j++) {
                const float p = __expf(SsT[j * 68 + srow] - m);
                l += p;
                const float4 v0 = *(const float4*)&Vs[j * 68 + sd0];
                const float4 v1 = *(const float4*)&Vs[j * 68 + sd0 + 4];
                const float4 v2 = *(const float4*)&Vs[j * 68 + sd0 + 8];
                const float4 v3 = *(const float4*)&Vs[j * 68 + sd0 + 12];
                oacc[0]  += p * v0.x; oacc[1]  += p * v0.y;
                oacc[2]  += p * v0.z; oacc[3]  += p * v0.w;
                oacc[4]  += p * v1.x; oacc[5]  += p * v1.y;
                oacc[6]  += p * v1.z; oacc[7]  += p * v1.w;
                oacc[8]  += p * v2.x; oacc[9]  += p * v2.y;
                oacc[10] += p * v2.z; oacc[11] += p * v2.w;
                oacc[12] += p * v3.x; oacc[13] += p * v3.y;
                oacc[14] += p * v3.z; oacc[15] += p * v3.w;
            }
        }
        __syncthreads();
    }

    // write: AO[(b*S + q), h*D + d]  (already the (0,2,1,3) transpose)
    const float inv = 1.0f / l;
    float* outp = AO + (size_t)(b * Ss + q0 + srow) * Ee + h * Dd + sd0;
    #pragma unroll
    for (int g = 0; g < 4; g++) {
        float4 r;
        r.x = oacc[g*4+0] * inv;
        r.y = oacc[g*4+1] * inv;
        r.z = oacc[g*4+2] * inv;
        r.w = oacc[g*4+3] * inv;
        *(float4*)(outp + g * 4) = r;
    }
}

// ------------------------- launch -------------------------
extern "C" void kernel_launch(void* const* d_in, const int* in_sizes, int n_in,
                              void* d_out, int out_size)
{
    (void)in_sizes; (void)n_in; (void)out_size;
    const float* src    = (const float*)d_in[0];
    const float* Wqkv   = (const float*)d_in[1];
    const float* bqkv   = (const float*)d_in[2];
    const float* Wout   = (const float*)d_in[3];
    const float* bout   = (const float*)d_in[4];
    const float* gamma1 = (const float*)d_in[5];
    const float* beta1  = (const float*)d_in[6];
    const float* gamma2 = (const float*)d_in[7];
    const float* beta2  = (const float*)d_in[8];
    const float* Wg     = (const float*)d_in[9];
    const float* bg     = (const float*)d_in[10];
    const float* Wv     = (const float*)d_in[11];
    const float* bv     = (const float*)d_in[12];
    const float* Wo     = (const float*)d_in[13];
    const float* bo     = (const float*)d_in[14];

    float *h, *qkv, *q, *k, *v, *attn, *x1, *gate;
    cudaGetSymbolAddress((void**)&h,    g_h);
    cudaGetSymbolAddress((void**)&qkv,  g_qkv);
    cudaGetSymbolAddress((void**)&q,    g_q);
    cudaGetSymbolAddress((void**)&k,    g_k);
    cudaGetSymbolAddress((void**)&v,    g_v);
    cudaGetSymbolAddress((void**)&attn, g_attn);
    cudaGetSymbolAddress((void**)&x1,   g_x1);
    cudaGetSymbolAddress((void**)&gate, g_gate);

    const int ATTN_SMEM = 4 * 64 * 68 * 4;  // 69632 B
    cudaFuncSetAttribute(attn_kernel, cudaFuncAttributeMaxDynamicSharedMemorySize, ATTN_SMEM);

    // 1) h1 = LN(src)
    ln_kernel<<<NT, 256>>>(src, gamma1, beta1, h);

    // 2) qkv = h1 @ Wqkv + bqkv
    sgemm128<0><<<dim3(3 * Ee / 128, NT / 128), 256>>>(h, Wqkv, bqkv, nullptr, qkv, NT, 3 * Ee, Ee);

    // 3) RoPE + split to [B,H,S,D]
    {
        const int total = Bb * Hh * Ss * 32;
        rope_split_kernel<<<(total + 255) / 256, 256>>>(qkv, q, k, v);
    }

    // 4) windowed attention -> attn [NT, E]
    attn_kernel<<<dim3(Ss / 64, Bb * Hh), 256, ATTN_SMEM>>>(q, k, v, attn);

    // 5) x1 = src + attn @ Wout + bout
    sgemm128<1><<<dim3(Ee / 128, NT / 128), 256>>>(attn, Wout, bout, src, x1, NT, Ee, Ee);

    // 6) h2 = LN(x1)
    ln_kernel<<<NT, 256>>>(x1, gamma2, beta2, h);

    // 7) gate = gelu(h2 @ Wg + bg)
    sgemm128<2><<<dim3(FFf / 128, NT / 128), 256>>>(h, Wg, bg, nullptr, gate, NT, FFf, Ee);

    // 8) gate = (h2 @ Wv + bv) * gate     (in-place gate*val)
    sgemm128<3><<<dim3(FFf / 128, NT / 128), 256>>>(h, Wv, bv, gate, gate, NT, FFf, Ee);

    // 9) out = x1 + gate @ Wo + bo
    sgemm128<1><<<dim3(Ee / 128, NT / 128), 256>>>(gate, Wo, bo, x1, (float*)d_out, NT, Ee, FFf);
}